// round 6
// baseline (speedup 1.0000x reference)
#include <cuda_runtime.h>
#include <math_constants.h>

// Problem constants
#define BB 128
#define CC 3
#define HH 256
#define WW 256
#define NSTEPS 64
#define NT 128                   // threads per CTA, 2 columns each
#define RB_PER_IMG 8             // row-blocks per image
#define ROWS_PER_CTA 32
#define NIMG (BB*CC)             // 384
#define NCTA (NIMG*RB_PER_IMG)   // 3072
#define NBINS 65                 // 64 real + 1 trash

// Deterministic per-CTA partial histograms + per-image completion counters.
__device__ int g_part[NCTA * NSTEPS];
__device__ int g_ctr[NIMG];      // zero-init; each launch returns it to zero

// bin = clip(ceil((f - 0.02)/RES), 0, 63); f > 0.98 (incl. INF sentinel) -> 64 (trash).
__device__ __forceinline__ int bin_of(float f) {
    constexpr double RES_D = (0.98 - 0.02) / 63.0;
    constexpr float RINV = (float)(1.0 / RES_D);
    constexpr float C    = (float)(-0.02 / RES_D);
    unsigned b = __float2uint_ru(fmaf(f, RINV, C));   // negatives saturate to 0
    return (int)min(b, (unsigned)(NBINS - 1));
}

struct Row { float l, x, y, r; };   // cols 2t-1, 2t, 2t+1, 2t+2

__device__ __forceinline__ Row load_row(const float* p, bool hasL, bool hasR) {
    Row r;
    float2 v = __ldg((const float2*)p);
    r.x = v.x; r.y = v.y;
    r.l = hasL ? __ldg(p - 1) : CUDART_INF_F;
    r.r = hasR ? __ldg(p + 2) : CUDART_INF_F;
    return r;
}

__device__ __forceinline__ Row inf_row() {
    Row r; r.l = r.x = r.y = r.r = CUDART_INF_F; return r;
}

// Per-pixel Euler weight: +1 vertex, -1 per dominated axis neighbor (edge
// attributed here), +1 per square where this pixel dominates the other 3
// corners. Total order = (value, position); position order means earlier
// neighbors (U, UL, UR, L) use <=, later ones (R, D, DL, DR) use <.
// INF sentinels are never dominated -> nonexistent cells never counted.
__device__ __forceinline__ void proc2(int* __restrict__ c,
                                      const Row& up, const Row& cu, const Row& dn) {
    const float a = cu.x, b = cu.y;
    const bool hba = (b < a);                 // shared horizontal comparison

    { // pixel at even column
        bool dL = (cu.l <= a), dU = (up.x <= a), dUL = (up.l <= a), dUR = (up.y <= a);
        bool dR = hba,         dD = (dn.x <  a), dDL = (dn.l <  a), dDR = (dn.y <  a);
        int w = 1 - (int)dL - (int)dR - (int)dU - (int)dD
              + (int)(dL && dU && dUL) + (int)(dR && dU && dUR)
              + (int)(dL && dD && dDL) + (int)(dR && dD && dDR);
        c[bin_of(a) * NT] += w;
    }
    { // pixel at odd column
        bool dL = !hba,         dU = (up.y <= b), dUL = (up.x <= b), dUR = (up.r <= b);
        bool dR = (cu.r <  b),  dD = (dn.y <  b), dDL = (dn.x <  b), dDR = (dn.r <  b);
        int w = 1 - (int)dL - (int)dR - (int)dU - (int)dD
              + (int)(dL && dU && dUL) + (int)(dR && dU && dUR)
              + (int)(dL && dD && dDL) + (int)(dR && dD && dDR);
        c[bin_of(b) * NT] += w;
    }
}

__global__ void __launch_bounds__(NT)
ecc_main(const float* __restrict__ x, float* __restrict__ out) {
    __shared__ int cnt[NBINS * NT];          // per-thread private stripes, conflict-free

    const int tid = threadIdx.x;
#pragma unroll
    for (int i = 0; i < NBINS; ++i) cnt[i * NT + tid] = 0;

    const int img = blockIdx.x >> 3;
    const int rb  = blockIdx.x & 7;
    const bool hasL = (tid > 0);
    const bool hasR = (tid < NT - 1);
    const float* p = x + (size_t)img * (HH * WW) + rb * ROWS_PER_CTA * WW + 2 * tid;

    int* c = cnt + tid;

    Row up = (rb > 0) ? load_row(p - WW, hasL, hasR) : inf_row();
    Row cu = load_row(p, hasL, hasR);

#pragma unroll 2
    for (int i = 0; i < ROWS_PER_CTA - 1; ++i) {
        Row dn = load_row(p + WW, hasL, hasR);
        proc2(c, up, cu, dn);
        up = cu; cu = dn; p += WW;
    }
    { // last row of this block: below is next block's first row, or image edge
        Row dn = (rb < RB_PER_IMG - 1) ? load_row(p + WW, hasL, hasR) : inf_row();
        proc2(c, up, cu, dn);
    }

    __syncthreads();

    // CTA reduction: warp w handles bins [w*16, w*16+16); trash bin 64 dropped.
    const int lane = tid & 31;
    const int wrp  = tid >> 5;
    int* outp = g_part + blockIdx.x * NSTEPS;
#pragma unroll
    for (int k = 0; k < 16; ++k) {
        const int bnum = wrp * 16 + k;
        int s = cnt[bnum * NT + lane] + cnt[bnum * NT + 32 + lane]
              + cnt[bnum * NT + 64 + lane] + cnt[bnum * NT + 96 + lane];
#pragma unroll
        for (int off = 16; off; off >>= 1)
            s += __shfl_xor_sync(0xFFFFFFFFu, s, off);
        if (lane == 0) outp[bnum] = s;
    }
    __syncthreads();

    // Fused finalize: the 8th CTA to finish an image sums its partials and scans.
    __shared__ int s_last;
    if (tid == 0) {
        __threadfence();                               // publish our g_part writes
        s_last = (atomicAdd(&g_ctr[img], 1) == RB_PER_IMG - 1) ? 1 : 0;
    }
    __syncthreads();

    if (s_last && wrp == 0) {
        if (lane == 0) g_ctr[img] = 0;                 // reset for next launch
        __threadfence();                               // acquire peers' g_part
        const int* pp = g_part + (size_t)img * RB_PER_IMG * NSTEPS;
        int s0 = 0, s1 = 0;
#pragma unroll
        for (int r = 0; r < RB_PER_IMG; ++r) {
            s0 += __ldcg(pp + r * NSTEPS + lane);
            s1 += __ldcg(pp + r * NSTEPS + lane + 32);
        }
        int v0 = s0;
#pragma unroll
        for (int off = 1; off < 32; off <<= 1) {
            int t = __shfl_up_sync(0xFFFFFFFFu, v0, off);
            if (lane >= off) v0 += t;
        }
        int tot = __shfl_sync(0xFFFFFFFFu, v0, 31);
        int v1 = s1;
#pragma unroll
        for (int off = 1; off < 32; off <<= 1) {
            int t = __shfl_up_sync(0xFFFFFFFFu, v1, off);
            if (lane >= off) v1 += t;
        }
        v1 += tot;
        out[(size_t)img * NSTEPS + lane]      = (float)v0;
        out[(size_t)img * NSTEPS + lane + 32] = (float)v1;
    }
}

extern "C" void kernel_launch(void* const* d_in, const int* in_sizes, int n_in,
                              void* d_out, int out_size) {
    (void)in_sizes; (void)n_in; (void)out_size;
    ecc_main<<<NCTA, NT>>>((const float*)d_in[0], (float*)d_out);
}

// round 7
// speedup vs baseline: 1.2452x; 1.2452x over previous
#include <cuda_runtime.h>
#include <math_constants.h>

// Problem constants
#define BB 128
#define CC 3
#define HH 256
#define WW 256
#define NSTEPS 64
#define NT 128                   // threads per CTA, 2 columns each
#define RB_PER_IMG 8             // row-blocks per image
#define ROWS_PER_CTA 32
#define NIMG (BB*CC)             // 384
#define NCTA (NIMG*RB_PER_IMG)   // 3072
#define NBINS 65                 // 64 real + 1 trash
#define CSTRIDE (NT + 2)         // short-counter stride: de-conflicts banks

// Deterministic per-CTA partial histograms (every slot written every launch).
__device__ int g_part[NCTA * NSTEPS];

// bin = clip(ceil((f - 0.02)/RES), 0, 63); f > 0.98 (incl. INF sentinel) -> 64 (trash).
__device__ __forceinline__ int bin_of(float f) {
    constexpr double RES_D = (0.98 - 0.02) / 63.0;
    constexpr float RINV = (float)(1.0 / RES_D);
    constexpr float C    = (float)(-0.02 / RES_D);
    unsigned b = __float2uint_ru(fmaf(f, RINV, C));   // negatives saturate to 0
    return (int)min(b, (unsigned)(NBINS - 1));
}

struct Row { float l, x, y, r; };   // cols 2t-1, 2t, 2t+1, 2t+2

__device__ __forceinline__ Row load_row(const float* p, bool hasL, bool hasR) {
    Row r;
    float2 v = __ldg((const float2*)p);
    r.x = v.x; r.y = v.y;
    r.l = hasL ? __ldg(p - 1) : CUDART_INF_F;
    r.r = hasR ? __ldg(p + 2) : CUDART_INF_F;
    return r;
}

__device__ __forceinline__ Row inf_row() {
    Row r; r.l = r.x = r.y = r.r = CUDART_INF_F; return r;
}

// Per-pixel Euler weight: +1 vertex, -1 per dominated axis neighbor, +1 per
// square where this pixel dominates the other 3 corners. Position tiebreak:
// earlier neighbors (U, UL, UR, L) use <=, later ones (R, D, DL, DR) use <.
// INF sentinels are never dominated -> nonexistent cells never counted.
// |w| <= 3, <=64 updates/thread -> per-thread per-bin sums fit int16.
__device__ __forceinline__ void proc2(short* __restrict__ c,
                                      const Row& up, const Row& cu, const Row& dn) {
    const float a = cu.x, b = cu.y;
    const bool hba = (b < a);                 // shared horizontal comparison

    { // pixel at even column
        bool dL = (cu.l <= a), dU = (up.x <= a), dUL = (up.l <= a), dUR = (up.y <= a);
        bool dR = hba,         dD = (dn.x <  a), dDL = (dn.l <  a), dDR = (dn.y <  a);
        int w = 1 - (int)dL - (int)dR - (int)dU - (int)dD
              + (int)(dL && dU && dUL) + (int)(dR && dU && dUR)
              + (int)(dL && dD && dDL) + (int)(dR && dD && dDR);
        c[bin_of(a) * CSTRIDE] += (short)w;
    }
    { // pixel at odd column
        bool dL = !hba,         dU = (up.y <= b), dUL = (up.x <= b), dUR = (up.r <= b);
        bool dR = (cu.r <  b),  dD = (dn.y <  b), dDL = (dn.x <  b), dDR = (dn.r <  b);
        int w = 1 - (int)dL - (int)dR - (int)dU - (int)dD
              + (int)(dL && dU && dUL) + (int)(dR && dU && dUR)
              + (int)(dL && dD && dDL) + (int)(dR && dD && dDR);
        c[bin_of(b) * CSTRIDE] += (short)w;
    }
}

__global__ void __launch_bounds__(NT, 12)
ecc_main(const float* __restrict__ x) {
    __shared__ short cnt[NBINS * CSTRIDE];   // 16.9 KB, per-thread private stripes

    const int tid = threadIdx.x;
#pragma unroll
    for (int i = 0; i < NBINS; ++i) cnt[i * CSTRIDE + tid] = 0;
    // no barrier needed: each thread only touches its own stripe until the reduce

    const int img = blockIdx.x >> 3;
    const int rb  = blockIdx.x & 7;
    const bool hasL = (tid > 0);
    const bool hasR = (tid < NT - 1);
    const float* p = x + (size_t)img * (HH * WW) + rb * ROWS_PER_CTA * WW + 2 * tid;

    short* c = cnt + tid;

    Row up = (rb > 0) ? load_row(p - WW, hasL, hasR) : inf_row();
    Row cu = load_row(p, hasL, hasR);

#pragma unroll 2
    for (int i = 0; i < ROWS_PER_CTA - 1; ++i) {
        Row dn = load_row(p + WW, hasL, hasR);
        proc2(c, up, cu, dn);
        up = cu; cu = dn; p += WW;
    }
    { // last row of this block: below is next block's first row, or image edge
        Row dn = (rb < RB_PER_IMG - 1) ? load_row(p + WW, hasL, hasR) : inf_row();
        proc2(c, up, cu, dn);
    }

    __syncthreads();

    // CTA reduction: warp w handles bins [w*16, w*16+16); trash bin 64 dropped.
    const int lane = tid & 31;
    const int wrp  = tid >> 5;
    int* outp = g_part + blockIdx.x * NSTEPS;
#pragma unroll
    for (int k = 0; k < 16; ++k) {
        const int bnum = wrp * 16 + k;
        int s = (int)cnt[bnum * CSTRIDE + lane]      + (int)cnt[bnum * CSTRIDE + 32 + lane]
              + (int)cnt[bnum * CSTRIDE + 64 + lane] + (int)cnt[bnum * CSTRIDE + 96 + lane];
#pragma unroll
        for (int off = 16; off; off >>= 1)
            s += __shfl_xor_sync(0xFFFFFFFFu, s, off);
        if (lane == 0) outp[bnum] = s;
    }
}

// Sum the 8 row-block partials per image, inclusive-scan the 64 bins, emit f32.
__global__ void __launch_bounds__(256)
ecc_final(float* __restrict__ out) {
    const int lane = threadIdx.x & 31;
    const int wpb  = threadIdx.x >> 5;
    const int img  = blockIdx.x * 8 + wpb;   // 48 blocks * 8 warps = 384 images

    const int* p = g_part + (size_t)img * RB_PER_IMG * NSTEPS;
    int s0 = 0, s1 = 0;
#pragma unroll
    for (int rb = 0; rb < RB_PER_IMG; ++rb) {
        s0 += __ldg(p + rb * NSTEPS + lane);
        s1 += __ldg(p + rb * NSTEPS + lane + 32);
    }

    // inclusive scan over 64 bins (lane holds bins lane and lane+32)
    int v0 = s0;
#pragma unroll
    for (int off = 1; off < 32; off <<= 1) {
        int t = __shfl_up_sync(0xFFFFFFFFu, v0, off);
        if (lane >= off) v0 += t;
    }
    int tot = __shfl_sync(0xFFFFFFFFu, v0, 31);
    int v1 = s1;
#pragma unroll
    for (int off = 1; off < 32; off <<= 1) {
        int t = __shfl_up_sync(0xFFFFFFFFu, v1, off);
        if (lane >= off) v1 += t;
    }
    v1 += tot;

    out[(size_t)img * NSTEPS + lane]      = (float)v0;
    out[(size_t)img * NSTEPS + lane + 32] = (float)v1;
}

extern "C" void kernel_launch(void* const* d_in, const int* in_sizes, int n_in,
                              void* d_out, int out_size) {
    (void)in_sizes; (void)n_in; (void)out_size;
    const float* x = (const float*)d_in[0];
    float* out = (float*)d_out;

    ecc_main<<<NCTA, NT>>>(x);
    ecc_final<<<NIMG / 8, 256>>>(out);
}

// round 8
// speedup vs baseline: 1.3850x; 1.1123x over previous
#include <cuda_runtime.h>
#include <math_constants.h>

// Problem constants
#define BB 128
#define CC 3
#define HH 256
#define WW 256
#define NSTEPS 64
#define NT 128                   // 64 column-threads x 2 row-strips
#define COLT 64                  // column threads per strip
#define RB_PER_IMG 4             // row-blocks per image (64 rows each, 2 strips of 32)
#define ROWS_PER_STRIP 32
#define NIMG (BB*CC)             // 384
#define NCTA (NIMG*RB_PER_IMG)   // 1536
#define NBINS 65                 // 64 real + 1 trash
#define CSTRIDE (NT + 2)         // short-counter stride: de-conflicts banks

// Deterministic per-CTA partial histograms (every slot written every launch).
__device__ int g_part[NCTA * NSTEPS];

// bin = clip(ceil((f - 0.02)/RES), 0, 63); f > 0.98 (incl. INF sentinel) -> 64 (trash).
__device__ __forceinline__ int bin_of(float f) {
    constexpr double RES_D = (0.98 - 0.02) / 63.0;
    constexpr float RINV = (float)(1.0 / RES_D);
    constexpr float C    = (float)(-0.02 / RES_D);
    unsigned b = __float2uint_ru(fmaf(f, RINV, C));   // negatives saturate to 0
    return (int)min(b, (unsigned)(NBINS - 1));
}

struct R4 { float l; float4 v; float r; };   // cols c-1, c..c+3, c+4

__device__ __forceinline__ R4 load_row(const float* p, bool hasL, bool hasR) {
    R4 r;
    r.v = __ldg((const float4*)p);
    r.l = hasL ? __ldg(p - 1) : CUDART_INF_F;
    r.r = hasR ? __ldg(p + 4) : CUDART_INF_F;
    return r;
}

__device__ __forceinline__ R4 inf_row() {
    R4 r; r.l = r.r = CUDART_INF_F;
    r.v = make_float4(CUDART_INF_F, CUDART_INF_F, CUDART_INF_F, CUDART_INF_F);
    return r;
}

// All-ones dominance masks. Position tiebreak: earlier neighbors (L,U,UL,UR)
// use <=, later (R,D,DL,DR) use <. INF sentinels never dominated.
// w = 1 + mL+mR+mU+mD - sum of quadrant masks (each -1 when p owns that square).
__device__ __forceinline__ void pix(short* __restrict__ c, float v,
                                    int mL, int mR,
                                    float u, float ul, float ur,
                                    float d, float dl, float dr) {
    int mU  = -(int)(u  <= v);
    int mUL = -(int)(ul <= v);
    int mUR = -(int)(ur <= v);
    int mD  = -(int)(d  <  v);
    int mDL = -(int)(dl <  v);
    int mDR = -(int)(dr <  v);
    int w = 1 + mL + mR + mU + mD
          - (mL & mU & mUL) - (mR & mU & mUR)
          - (mL & mD & mDL) - (mR & mD & mDR);
    c[bin_of(v) * CSTRIDE] += (short)w;
}

__device__ __forceinline__ void proc4(short* __restrict__ c,
                                      const R4& up, const R4& cu, const R4& dn) {
    // shared horizontal masks (h_i = mask(left_of_i <= v_i)); mR = ~h_{i+1}
    int h0 = -(int)(cu.l   <= cu.v.x);
    int h1 = -(int)(cu.v.x <= cu.v.y);
    int h2 = -(int)(cu.v.y <= cu.v.z);
    int h3 = -(int)(cu.v.z <= cu.v.w);
    int h4 = -(int)(cu.r   <  cu.v.w);   // right-of-pixel3 (later -> <)

    pix(c, cu.v.x, h0, ~h1, up.v.x, up.l,   up.v.y, dn.v.x, dn.l,   dn.v.y);
    pix(c, cu.v.y, h1, ~h2, up.v.y, up.v.x, up.v.z, dn.v.y, dn.v.x, dn.v.z);
    pix(c, cu.v.z, h2, ~h3, up.v.z, up.v.y, up.v.w, dn.v.z, dn.v.y, dn.v.w);
    pix(c, cu.v.w, h3, h4,  up.v.w, up.v.z, up.r,   dn.v.w, dn.v.z, dn.r);
}

__global__ void __launch_bounds__(NT, 10)
ecc_main(const float* __restrict__ x) {
    __shared__ short cnt[NBINS * CSTRIDE];   // 16.9 KB, per-thread private stripes

    const int tid = threadIdx.x;
#pragma unroll
    for (int i = 0; i < NBINS; ++i) cnt[i * CSTRIDE + tid] = 0;
    // no barrier: each thread touches only its own stripe until the reduce

    const int img   = blockIdx.x >> 2;
    const int rb    = blockIdx.x & 3;
    const int strip = tid >> 6;              // 0 or 1
    const int ct    = tid & (COLT - 1);
    const int col   = ct * 4;
    const int g0    = rb * 64 + strip * ROWS_PER_STRIP;
    const bool hasL = (ct > 0);
    const bool hasR = (ct < COLT - 1);
    const float* p  = x + (size_t)img * (HH * WW) + g0 * WW + col;

    short* c = cnt + tid;

    R4 up = (g0 > 0) ? load_row(p - WW, hasL, hasR) : inf_row();
    R4 cu = load_row(p, hasL, hasR);

#pragma unroll 2
    for (int i = 0; i < ROWS_PER_STRIP - 1; ++i) {
        R4 dn = load_row(p + WW, hasL, hasR);
        proc4(c, up, cu, dn);
        up = cu; cu = dn; p += WW;
    }
    { // last row of strip: below is next strip/block's first row, or image edge
        R4 dn = (g0 + ROWS_PER_STRIP < HH) ? load_row(p + WW, hasL, hasR) : inf_row();
        proc4(c, up, cu, dn);
    }

    __syncthreads();

    // CTA reduction: warp w handles bins [w*16, w*16+16); trash bin 64 dropped.
    const int lane = tid & 31;
    const int wrp  = tid >> 5;
    int* outp = g_part + blockIdx.x * NSTEPS;
#pragma unroll
    for (int k = 0; k < 16; ++k) {
        const int bnum = wrp * 16 + k;
        int s = (int)cnt[bnum * CSTRIDE + lane]      + (int)cnt[bnum * CSTRIDE + 32 + lane]
              + (int)cnt[bnum * CSTRIDE + 64 + lane] + (int)cnt[bnum * CSTRIDE + 96 + lane];
#pragma unroll
        for (int off = 16; off; off >>= 1)
            s += __shfl_xor_sync(0xFFFFFFFFu, s, off);
        if (lane == 0) outp[bnum] = s;
    }
}

// Sum the 4 row-block partials per image, inclusive-scan the 64 bins, emit f32.
__global__ void __launch_bounds__(256)
ecc_final(float* __restrict__ out) {
    const int lane = threadIdx.x & 31;
    const int wpb  = threadIdx.x >> 5;
    const int img  = blockIdx.x * 8 + wpb;   // 48 blocks * 8 warps = 384 images

    const int* p = g_part + (size_t)img * RB_PER_IMG * NSTEPS;
    int s0 = 0, s1 = 0;
#pragma unroll
    for (int rb = 0; rb < RB_PER_IMG; ++rb) {
        s0 += __ldg(p + rb * NSTEPS + lane);
        s1 += __ldg(p + rb * NSTEPS + lane + 32);
    }

    // inclusive scan over 64 bins (lane holds bins lane and lane+32)
    int v0 = s0;
#pragma unroll
    for (int off = 1; off < 32; off <<= 1) {
        int t = __shfl_up_sync(0xFFFFFFFFu, v0, off);
        if (lane >= off) v0 += t;
    }
    int tot = __shfl_sync(0xFFFFFFFFu, v0, 31);
    int v1 = s1;
#pragma unroll
    for (int off = 1; off < 32; off <<= 1) {
        int t = __shfl_up_sync(0xFFFFFFFFu, v1, off);
        if (lane >= off) v1 += t;
    }
    v1 += tot;

    out[(size_t)img * NSTEPS + lane]      = (float)v0;
    out[(size_t)img * NSTEPS + lane + 32] = (float)v1;
}

extern "C" void kernel_launch(void* const* d_in, const int* in_sizes, int n_in,
                              void* d_out, int out_size) {
    (void)in_sizes; (void)n_in; (void)out_size;
    const float* x = (const float*)d_in[0];
    float* out = (float*)d_out;

    ecc_main<<<NCTA, NT>>>(x);
    ecc_final<<<NIMG / 8, 256>>>(out);
}